// round 3
// baseline (speedup 1.0000x reference)
#include <cuda_runtime.h>

#define DIM 16

// ---------- scalar complex helpers ----------
__device__ __forceinline__ float2 cmul(float2 a, float2 b){
    return make_float2(fmaf(a.x, b.x, -a.y * b.y),
                       fmaf(a.x, b.y,  a.y * b.x));
}
__device__ __forceinline__ float2 cmadd(float2 a, float2 b, float2 acc){
    acc.x = fmaf(a.x, b.x, fmaf(-a.y, b.y, acc.x));
    acc.y = fmaf(a.x, b.y, fmaf( a.y, b.x, acc.y));
    return acc;
}
__device__ __forceinline__ void mm2(const float2* A, const float2* B, float2* C){
    C[0] = cmadd(A[1], B[2], cmul(A[0], B[0]));
    C[1] = cmadd(A[1], B[3], cmul(A[0], B[1]));
    C[2] = cmadd(A[3], B[2], cmul(A[2], B[0]));
    C[3] = cmadd(A[3], B[3], cmul(A[2], B[1]));
}

// Single fused kernel: per-block redundant setup (tiny) + batch computation.
__global__ void __launch_bounds__(256) vqc_fused(
    const float4* __restrict__ x, const float* __restrict__ theta,
    const float* __restrict__ lmbd, float4* __restrict__ out, int B)
{
    __shared__ float2 sT[4][4][4];    // folded Rz*Ry*Rx per (theta-layer, qubit)
    __shared__ float2 sP[3][4][2];    // top row (00,01) of P_l,i (SU(2))
    __shared__ float2 sPsi0[DIM];     // CZ * T0 |0>
    __shared__ float  sL[12];

    const int t = threadIdx.x;

    // ---- stage 1: build the 16 theta-gates T[l][i] ----
    if (t < 16){
        int l = t >> 2, i = t & 3;
        float t0 = theta[t*3 + 0];
        float t1 = theta[t*3 + 1];
        float t2 = theta[t*3 + 2];
        float cx, sx, cy, sy, cz, sz;
        sincosf(0.5f*t0, &sx, &cx);
        sincosf(0.5f*t1, &sy, &cy);
        sincosf(0.5f*t2, &sz, &cz);
        float2 RX[4] = {{cx,0.f},{0.f,-sx},{0.f,-sx},{cx,0.f}};
        float2 RY[4] = {{cy,0.f},{-sy,0.f},{sy,0.f},{cy,0.f}};
        float2 RZ[4] = {{cz,-sz},{0.f,0.f},{0.f,0.f},{cz,sz}};
        float2 YX[4], M[4];
        mm2(RY, RX, YX);
        mm2(RZ, YX, M);
        #pragma unroll
        for (int e = 0; e < 4; e++) sT[l][i][e] = M[e];
    }
    if (t >= 32 && t < 44) sL[t - 32] = lmbd[t - 32];
    __syncthreads();

    // ---- stage 2: fold post-matrices P_l = T_{l+1}*F (top row only) + psi0 ----
    if (t < 12){
        int l = t >> 2, i = t & 3;
        float2 G0, G1;
        if (l < 2){
            G0 = cmadd(sT[l+1][i][1], sT[3][i][2], cmul(sT[l+1][i][0], sT[3][i][0]));
            G1 = cmadd(sT[l+1][i][1], sT[3][i][3], cmul(sT[l+1][i][0], sT[3][i][1]));
        } else {
            G0 = sT[3][i][0];
            G1 = sT[3][i][1];
        }
        sP[l][i][0] = G0;
        sP[l][i][1] = G1;
    }
    if (t >= 16 && t < 32){
        int s = t - 16;
        float2 v = make_float2(1.f, 0.f);
        #pragma unroll
        for (int i = 0; i < 4; i++){
            int bi = (s >> (3 - i)) & 1;
            v = cmul(v, sT[0][i][bi*2 + 0]);   // column 0 of T0_i
        }
        int b0=(s>>3)&1, b1=(s>>2)&1, b2=(s>>1)&1, b3=s&1;
        int e = (b0&b1) ^ (b1&b2) ^ (b2&b3) ^ (b0&b3);
        if (e) { v.x = -v.x; v.y = -v.y; }
        sPsi0[s] = v;
    }
    __syncthreads();

    // ---- main per-element circuit ----
    int b = blockIdx.x * blockDim.x + t;
    if (b >= B) return;

    float4 xv = x[b];
    float xq[4] = {xv.x, xv.y, xv.z, xv.w};

    float2 r[DIM];
    #pragma unroll
    for (int s = 0; s < DIM; s++) r[s] = sPsi0[s];

    #pragma unroll
    for (int l = 0; l < 3; l++){
        float ch[4], sh[4];
        #pragma unroll
        for (int i = 0; i < 4; i++){
            float a = sL[l*4 + i] * xq[i];
            __sincosf(0.5f * a, &sh[i], &ch[i]);
        }
        #pragma unroll
        for (int i = 0; i < 4; i++){
            // z-angle shares trig with a0 (qubits 0,1) / a1 (qubits 2,3)
            float cz = (i < 2) ? ch[0] : ch[1];
            float sz = (i < 2) ? sh[0] : sh[1];
            float ci = ch[i], si = sh[i];
            float c2 = ci*ci, s2 = si*si, sc = si*ci;
            // M = Rz(z)*Ry(a)*Rx(a), SU(2): only top row needed
            float2 M00 = make_float2(fmaf(cz, c2,  sz*s2), fmaf(cz, s2, -sz*c2));
            float2 M01 = make_float2(-sc*(cz + sz), sc*(sz - cz));
            float2 M10 = make_float2(-M01.x,  M01.y);   // -conj(M01)
            float2 M11 = make_float2( M00.x, -M00.y);   //  conj(M00)
            // G = P * M (SU(2): top row, bottom row derived)
            float2 P00 = sP[l][i][0], P01 = sP[l][i][1];
            float2 G00 = cmadd(P01, M10, cmul(P00, M00));
            float2 G01 = cmadd(P01, M11, cmul(P00, M01));
            float2 G10 = make_float2(-G01.x,  G01.y);
            float2 G11 = make_float2( G00.x, -G00.y);
            // apply on qubit i (stride 8>>i)
            const int st = 8 >> i;
            #pragma unroll
            for (int j = 0; j < DIM; j++){
                if (j & st) continue;
                float2 p0 = r[j], p1 = r[j + st];
                r[j]      = cmadd(G01, p1, cmul(G00, p0));
                r[j + st] = cmadd(G11, p1, cmul(G10, p0));
            }
        }
        if (l < 2){   // CZ diag: -1 at states 3, 6, 9, 12 (signs fold into FFMAs)
            r[3].x  = -r[3].x;  r[3].y  = -r[3].y;
            r[6].x  = -r[6].x;  r[6].y  = -r[6].y;
            r[9].x  = -r[9].x;  r[9].y  = -r[9].y;
            r[12].x = -r[12].x; r[12].y = -r[12].y;
        }
    }

    // probs + Walsh-tree reduction to 4 <Z_q> values
    float ps[DIM];
    #pragma unroll
    for (int s = 0; s < DIM; s++)
        ps[s] = fmaf(r[s].x, r[s].x, r[s].y * r[s].y);

    float d3 = (ps[0]-ps[1]) + (ps[2]-ps[3]) + (ps[4]-ps[5]) + (ps[6]-ps[7])
             + (ps[8]-ps[9]) + (ps[10]-ps[11]) + (ps[12]-ps[13]) + (ps[14]-ps[15]);
    float e[8];
    #pragma unroll
    for (int k = 0; k < 8; k++) e[k] = ps[2*k] + ps[2*k+1];
    float d2 = (e[0]-e[1]) + (e[2]-e[3]) + (e[4]-e[5]) + (e[6]-e[7]);
    float f[4];
    #pragma unroll
    for (int k = 0; k < 4; k++) f[k] = e[2*k] + e[2*k+1];
    float d1 = (f[0]-f[1]) + (f[2]-f[3]);
    float o0 = (f[0] + f[1]) - (f[2] + f[3]);

    out[b] = make_float4(o0, d1, d2, d3);
}

extern "C" void kernel_launch(void* const* d_in, const int* in_sizes, int n_in,
                              void* d_out, int out_size)
{
    const float* x     = (const float*)d_in[0];
    const float* theta = (const float*)d_in[1];
    const float* lmbd  = (const float*)d_in[2];
    int B = in_sizes[0] / 4;

    vqc_fused<<<(B + 255) / 256, 256>>>((const float4*)x, theta, lmbd,
                                        (float4*)d_out, B);
}

// round 5
// speedup vs baseline: 1.0867x; 1.0867x over previous
#include <cuda_runtime.h>

#define DIM 16
typedef unsigned long long ull;

// ---------- packed f32x2 helpers ----------
__device__ __forceinline__ ull pk2(float lo, float hi){
    ull r; asm("mov.b64 %0, {%1, %2};" : "=l"(r) : "f"(lo), "f"(hi)); return r;
}
__device__ __forceinline__ ull dup2(float v){ return pk2(v, v); }
__device__ __forceinline__ ull fma2(ull a, ull b, ull c){
    ull d; asm("fma.rn.f32x2 %0, %1, %2, %3;" : "=l"(d) : "l"(a), "l"(b), "l"(c)); return d;
}
__device__ __forceinline__ ull mul2(ull a, ull b){
    ull d; asm("mul.rn.f32x2 %0, %1, %2;" : "=l"(d) : "l"(a), "l"(b)); return d;
}
__device__ __forceinline__ ull swp(ull v){
    unsigned lo, hi; asm("mov.b64 {%0, %1}, %2;" : "=r"(lo), "=r"(hi) : "l"(v));
    ull r; asm("mov.b64 %0, {%1, %2};" : "=l"(r) : "r"(hi), "r"(lo)); return r;
}
__device__ __forceinline__ void unpk(ull v, float& lo, float& hi){
    asm("mov.b64 {%0, %1}, %2;" : "=f"(lo), "=f"(hi) : "l"(v));
}

// ---------- scalar complex helpers (setup + G build) ----------
__device__ __forceinline__ float2 cmul(float2 a, float2 b){
    return make_float2(fmaf(a.x, b.x, -a.y * b.y),
                       fmaf(a.x, b.y,  a.y * b.x));
}
__device__ __forceinline__ float2 cmadd(float2 a, float2 b, float2 acc){
    acc.x = fmaf(a.x, b.x, fmaf(-a.y, b.y, acc.x));
    acc.y = fmaf(a.x, b.y, fmaf( a.y, b.x, acc.y));
    return acc;
}
__device__ __forceinline__ void mm2(const float2* A, const float2* B, float2* C){
    C[0] = cmadd(A[1], B[2], cmul(A[0], B[0]));
    C[1] = cmadd(A[1], B[3], cmul(A[0], B[1]));
    C[2] = cmadd(A[3], B[2], cmul(A[2], B[0]));
    C[3] = cmadd(A[3], B[3], cmul(A[2], B[1]));
}

__global__ void __launch_bounds__(256) vqc_fused(
    const float4* __restrict__ x, const float* __restrict__ theta,
    const float* __restrict__ lmbd, float4* __restrict__ out, int B)
{
    __shared__ float2 sT[4][4][4];    // folded Rz*Ry*Rx per (theta-layer, qubit)
    __shared__ float2 sP[3][4][2];    // top row (00,01) of P_l,i (SU(2))
    __shared__ float2 sPsi0[DIM];     // CZ * T0 |0>
    __shared__ float  sL[12];

    const int t = threadIdx.x;

    // ---- prologue stage 1: the 16 theta-gates T[l][i] ----
    if (t < 16){
        int l = t >> 2, i = t & 3;
        float t0 = theta[t*3 + 0], t1 = theta[t*3 + 1], t2 = theta[t*3 + 2];
        float cx, sx, cy, sy, cz, sz;
        sincosf(0.5f*t0, &sx, &cx);
        sincosf(0.5f*t1, &sy, &cy);
        sincosf(0.5f*t2, &sz, &cz);
        float2 RX[4] = {{cx,0.f},{0.f,-sx},{0.f,-sx},{cx,0.f}};
        float2 RY[4] = {{cy,0.f},{-sy,0.f},{sy,0.f},{cy,0.f}};
        float2 RZ[4] = {{cz,-sz},{0.f,0.f},{0.f,0.f},{cz,sz}};
        float2 YX[4], M[4];
        mm2(RY, RX, YX);
        mm2(RZ, YX, M);
        #pragma unroll
        for (int e = 0; e < 4; e++) sT[l][i][e] = M[e];
    }
    if (t >= 32 && t < 44) sL[t - 32] = lmbd[t - 32];
    __syncthreads();

    // ---- prologue stage 2: fold P_l (top row) + psi0 ----
    if (t < 12){
        int l = t >> 2, i = t & 3;
        float2 G0, G1;
        if (l < 2){
            G0 = cmadd(sT[l+1][i][1], sT[3][i][2], cmul(sT[l+1][i][0], sT[3][i][0]));
            G1 = cmadd(sT[l+1][i][1], sT[3][i][3], cmul(sT[l+1][i][0], sT[3][i][1]));
        } else {
            G0 = sT[3][i][0];
            G1 = sT[3][i][1];
        }
        sP[l][i][0] = G0;
        sP[l][i][1] = G1;
    }
    if (t >= 16 && t < 32){
        int s = t - 16;
        float2 v = make_float2(1.f, 0.f);
        #pragma unroll
        for (int i = 0; i < 4; i++){
            int bi = (s >> (3 - i)) & 1;
            v = cmul(v, sT[0][i][bi*2 + 0]);
        }
        int b0=(s>>3)&1, b1=(s>>2)&1, b2=(s>>1)&1, b3=s&1;
        int e = (b0&b1) ^ (b1&b2) ^ (b2&b3) ^ (b0&b3);
        if (e) { v.x = -v.x; v.y = -v.y; }
        sPsi0[s] = v;
    }
    __syncthreads();

    // ---- main per-element circuit (split-complex packed layout) ----
    int b = blockIdx.x * blockDim.x + t;
    if (b >= B) return;

    float4 xv = x[b];
    float xq[4] = {xv.x, xv.y, xv.z, xv.w};

    // R[m] = (re_{2m}, re_{2m+1}),  I[m] = (im_{2m}, im_{2m+1})
    ull Rr[8], Ii[8];
    #pragma unroll
    for (int m = 0; m < 8; m++){
        float2 a = sPsi0[2*m], c = sPsi0[2*m+1];
        Rr[m] = pk2(a.x, c.x);
        Ii[m] = pk2(a.y, c.y);
    }

    #pragma unroll
    for (int l = 0; l < 3; l++){
        float ch[4], sh[4];
        #pragma unroll
        for (int i = 0; i < 4; i++){
            float a = sL[l*4 + i] * xq[i];
            __sincosf(0.5f * a, &sh[i], &ch[i]);
        }
        #pragma unroll
        for (int i = 0; i < 4; i++){
            // z-angle shares trig with a0 (qubits 0,1) / a1 (qubits 2,3)
            float cz = (i < 2) ? ch[0] : ch[1];
            float sz = (i < 2) ? sh[0] : sh[1];
            float ci = ch[i], si = sh[i];
            float c2 = ci*ci, s2 = si*si, sc = si*ci;
            float2 M00 = make_float2(fmaf(cz, c2,  sz*s2), fmaf(cz, s2, -sz*c2));
            float2 M01 = make_float2(-sc*(cz + sz), sc*(sz - cz));
            float2 M10 = make_float2(-M01.x,  M01.y);
            float2 M11 = make_float2( M00.x, -M00.y);
            float2 P00 = sP[l][i][0], P01 = sP[l][i][1];
            float2 G00 = cmadd(P01, M10, cmul(P00, M00));
            float2 G01 = cmadd(P01, M11, cmul(P00, M01));
            // G10 = (-G01.x, G01.y), G11 = (G00.x, -G00.y)

            if (i < 3){
                // both packed lanes transform identically: pure FFMA2, no swaps
                ull pG00x  = dup2( G00.x), pG00y  = dup2( G00.y);
                ull pnG00y = dup2(-G00.y);
                ull pG01x  = dup2( G01.x), pnG01x = dup2(-G01.x);
                ull pG01y  = dup2( G01.y), pnG01y = dup2(-G01.y);
                const int hs = 4 >> i;   // slot stride (st/2)
                #pragma unroll
                for (int m = 0; m < 8; m++){
                    if (m & hs) continue;
                    const int u = m, v = m + hs;
                    ull R0 = Rr[u], I0 = Ii[u], R1 = Rr[v], I1 = Ii[v];
                    Rr[u] = fma2(pnG01y,I1, fma2(pG01x ,R1, fma2(pnG00y,I0, mul2(pG00x ,R0))));
                    Ii[u] = fma2(pG01x ,I1, fma2(pG01y ,R1, fma2(pG00x ,I0, mul2(pG00y ,R0))));
                    Rr[v] = fma2(pG00y ,I1, fma2(pG00x ,R1, fma2(pnG01y,I0, mul2(pnG01x,R0))));
                    Ii[v] = fma2(pG00x ,I1, fma2(pnG00y,R1, fma2(pnG01x,I0, mul2(pG01y ,R0))));
                }
            } else {
                // qubit 3 (stride 1): partners share a packed register -> swaps
                // lane algebra (lo = p0, hi = p1):
                //  Rr' = c1.R + c2v.Rs + c3.I + c4.Is
                //   lo: G00.x*R0 + G01.x*R1 − G00.y*I0 − G01.y*I1
                //   hi: G00.x*R1 − G01.x*R0 + G00.y*I1 − G01.y*I0
                //  Ii' = c1.I + c2v.Is + c5.R + c6.Rs
                //   lo: G00.x*I0 + G01.x*I1 + G00.y*R0 + G01.y*R1
                //   hi: G00.x*I1 − G01.x*I0 − G00.y*R1 + G01.y*R0
                ull c1  = dup2( G00.x);
                ull c2v = pk2( G01.x, -G01.x);
                ull c3  = pk2(-G00.y,  G00.y);
                ull c4  = dup2(-G01.y);          // FIXED (was pk2(-G01.y, G01.y))
                ull c5  = pk2( G00.y, -G00.y);
                ull c6  = dup2( G01.y);
                #pragma unroll
                for (int m = 0; m < 8; m++){
                    ull R = Rr[m], I = Ii[m];
                    ull Rs = swp(R), Is = swp(I);
                    Rr[m] = fma2(c4, Is, fma2(c3, I, fma2(c2v, Rs, mul2(c1, R))));
                    Ii[m] = fma2(c6, Rs, fma2(c5, R, fma2(c2v, Is, mul2(c1, I))));
                }
            }
        }
        if (l < 2){
            // CZ: flip states 3 (slot1 hi), 6 (slot3 lo), 9 (slot4 hi), 12 (slot6 lo)
            const ull HI = 0x8000000000000000ull, LO = 0x80000000ull;
            Rr[1] ^= HI; Ii[1] ^= HI;
            Rr[3] ^= LO; Ii[3] ^= LO;
            Rr[4] ^= HI; Ii[4] ^= HI;
            Rr[6] ^= LO; Ii[6] ^= LO;
        }
    }

    // probs + Walsh-tree reduction
    float ps[DIM];
    #pragma unroll
    for (int m = 0; m < 8; m++){
        ull q = fma2(Ii[m], Ii[m], mul2(Rr[m], Rr[m]));
        unpk(q, ps[2*m], ps[2*m+1]);
    }
    float d3 = (ps[0]-ps[1]) + (ps[2]-ps[3]) + (ps[4]-ps[5]) + (ps[6]-ps[7])
             + (ps[8]-ps[9]) + (ps[10]-ps[11]) + (ps[12]-ps[13]) + (ps[14]-ps[15]);
    float e[8];
    #pragma unroll
    for (int k = 0; k < 8; k++) e[k] = ps[2*k] + ps[2*k+1];
    float d2 = (e[0]-e[1]) + (e[2]-e[3]) + (e[4]-e[5]) + (e[6]-e[7]);
    float f[4];
    #pragma unroll
    for (int k = 0; k < 4; k++) f[k] = e[2*k] + e[2*k+1];
    float d1 = (f[0]-f[1]) + (f[2]-f[3]);
    float o0 = (f[0] + f[1]) - (f[2] + f[3]);

    out[b] = make_float4(o0, d1, d2, d3);
}

extern "C" void kernel_launch(void* const* d_in, const int* in_sizes, int n_in,
                              void* d_out, int out_size)
{
    const float* x     = (const float*)d_in[0];
    const float* theta = (const float*)d_in[1];
    const float* lmbd  = (const float*)d_in[2];
    int B = in_sizes[0] / 4;

    vqc_fused<<<(B + 255) / 256, 256>>>((const float4*)x, theta, lmbd,
                                        (float4*)d_out, B);
}